// round 11
// baseline (speedup 1.0000x reference)
#include <cuda_runtime.h>
#include <cuda_fp16.h>
#include <cstdint>

// ---------------- problem constants ----------------
#define MDIM 65536      // B*S
#define KDIM 768        // D
#define NDIM 2304       // 3*D
#define RNK  4

#define BM 128
#define BN 256
#define BK 32           // halves per K-step
#define KITERS (KDIM / BK)   // 24
#define STAGES 4
#define NTILES 4608     // (MDIM/BM) * (NDIM/BN) = 512*9
#define GRID   148      // persistent: one CTA per SM

// smem stage layout: A 128 rows x 80B (32 halves + 16B pad), B 256 rows x 80B
#define AROW_B   80
#define A_BYTES  (128 * AROW_B)      // 10240
#define B_BYTES  (256 * AROW_B)      // 20480
#define STAGE_B  (A_BYTES + B_BYTES) // 30720
#define SMEM_TOTAL (STAGES * STAGE_B) // 122880

// ---------------- device scratch (no allocations allowed) ----------------
__device__ __half g_Wh[(size_t)NDIM * KDIM];   // folded fp16 W_eff (3.4 MB)

// ---------------- helpers ----------------
__device__ __forceinline__ uint32_t smem_u32(const void* p) {
    return (uint32_t)__cvta_generic_to_shared(p);
}

__device__ __forceinline__ void cp_async16(uint32_t s, const void* g) {
    asm volatile("cp.async.cg.shared.global [%0], [%1], 16;" :: "r"(s), "l"(g));
}
#define CP_COMMIT() asm volatile("cp.async.commit_group;" ::: "memory")

#define LDSM_X4(r0, r1, r2, r3, addr) \
    asm volatile("ldmatrix.sync.aligned.m8n8.x4.shared.b16 {%0,%1,%2,%3}, [%4];" \
        : "=r"(r0), "=r"(r1), "=r"(r2), "=r"(r3) : "r"(addr))

// fp16-accumulate MMA (same rate as f32-acc on this chip, but halves acc regs)
#define MMA16816_F16(d, a0, a1, a2, a3, b0, b1) \
    asm volatile("mma.sync.aligned.m16n8k16.row.col.f16.f16.f16.f16 " \
        "{%0,%1}, {%2,%3,%4,%5}, {%6,%7}, {%0,%1};" \
        : "+r"((d)[0]), "+r"((d)[1]) \
        : "r"(a0), "r"(a1), "r"(a2), "r"(a3), "r"(b0), "r"(b1))

// convert 8 fp32 -> 8 fp16 and store 16B to smem
__device__ __forceinline__ void sts_a16(uint32_t dst, float4 p0, float4 p1) {
    __half2 h0 = __floats2half2_rn(p0.x, p0.y);
    __half2 h1 = __floats2half2_rn(p0.z, p0.w);
    __half2 h2 = __floats2half2_rn(p1.x, p1.y);
    __half2 h3 = __floats2half2_rn(p1.z, p1.w);
    asm volatile("st.shared.v4.b32 [%0], {%1,%2,%3,%4};" :: "r"(dst),
        "r"(*reinterpret_cast<uint32_t*>(&h0)), "r"(*reinterpret_cast<uint32_t*>(&h1)),
        "r"(*reinterpret_cast<uint32_t*>(&h2)), "r"(*reinterpret_cast<uint32_t*>(&h3))
        : "memory");
}

// ---------------- prep kernel (W fold + fp16) ----------------
__global__ void prep_w_kernel(const float* __restrict__ W,
                              const float* __restrict__ Aq, const float* __restrict__ Bq,
                              const float* __restrict__ Av, const float* __restrict__ Bv,
                              const float* __restrict__ s0) {
    int idx = blockIdx.x * 256 + threadIdx.x;   // exact: NDIM*KDIM
    int e = idx / KDIM;
    int d = idx - e * KDIM;
    float w = W[idx];
    float s = s0[0];
    if (e < KDIM) {                              // q slice
        float acc = 0.f;
#pragma unroll
        for (int r = 0; r < RNK; r++) acc += Aq[r * KDIM + d] * Bq[e * RNK + r];
        w = fmaf(s, acc, w);
    } else if (e >= 2 * KDIM) {                  // v slice
        int e2 = e - 2 * KDIM;
        float acc = 0.f;
#pragma unroll
        for (int r = 0; r < RNK; r++) acc += Av[r * KDIM + d] * Bv[e2 * RNK + r];
        w = fmaf(s, acc, w);
    }
    g_Wh[idx] = __float2half_rn(w);
}

// ------- persistent GEMM: fp32-X fused convert, fp16 accum (2 chains) -------
__global__ __launch_bounds__(512, 1)
void gemm_persist(const float* __restrict__ X, const __half* __restrict__ W,
                  const float* __restrict__ bias, float* __restrict__ out) {
    extern __shared__ char smem[];
    uint32_t sb = smem_u32(smem);
    int tid = threadIdx.x;
    int lane = tid & 31;
    int wid = tid >> 5;
    int warp_m = wid & 3;     // 4 m-warps
    int warp_n = wid >> 2;    // 4 n-warps

    // ---- fixed per-thread offsets ----
    int arow = tid >> 2, ac = tid & 3;
    // A: LDG 32B fp32 per thread (2 float4), STS 16B fp16
    uint32_t aDst = sb + arow * AROW_B + ac * 16;
    // B: cp.async 2x16B per thread
    uint32_t bDst0 = sb + A_BYTES + arow * AROW_B + ac * 16;
    uint32_t bDst1 = bDst0 + 128 * AROW_B;

    // ldmatrix lane addresses (same as R8)
    uint32_t aLds = sb + (warp_m * 32 + (lane & 15)) * AROW_B + ((lane >> 4) * 16);
    int t_ = lane >> 3;
    uint32_t bLds = sb + A_BYTES + (warp_n * 64 + (lane & 7) + (t_ >> 1) * 8) * AROW_B
                    + (t_ & 1) * 16;

    // ---- load cursors (continuous across tiles) ----
    int t0 = blockIdx.x;
    int tA = t0, aK, aV = 1;
    const float* aL = X + (size_t)((tA / 9) * BM + arow) * KDIM + ac * 8;
    int tB = t0, bK, bV = 1;
    const __half* bL = W + (size_t)((tB % 9) * BN + arow) * KDIM + ac * 8;

    // ---- prologue ----
    // B stages 0..2 via cp.async (3 groups)
#pragma unroll
    for (int s = 0; s < 3; s++) {
        uint32_t so = s * STAGE_B;
        cp_async16(bDst0 + so, bL + s * BK);
        cp_async16(bDst1 + so, bL + (size_t)128 * KDIM + s * BK);
        CP_COMMIT();
    }
    bK = 3;
    // A stage 0: LDG -> convert -> STS (slot 0); then preload A stage 1
    float4 pa0 = *reinterpret_cast<const float4*>(aL);
    float4 pa1 = *reinterpret_cast<const float4*>(aL + 4);
    sts_a16(aDst, pa0, pa1);
    pa0 = *reinterpret_cast<const float4*>(aL + BK);
    pa1 = *reinterpret_cast<const float4*>(aL + BK + 4);
    aK = 2;

    // ---- persistent tile loop ----
    for (int t = t0; t < NTILES; t += GRID) {
        int m0 = (t / 9) * BM;
        int n0 = (t % 9) * BN;

        // fp16 accumulators: 2 K-chains (accuracy), reset per tile
        uint32_t acch[2][2][8][2];
#pragma unroll
        for (int c = 0; c < 2; c++)
#pragma unroll
            for (int mi = 0; mi < 2; mi++)
#pragma unroll
                for (int nj = 0; nj < 8; nj++) {
                    acch[c][mi][nj][0] = 0u;
                    acch[c][mi][nj][1] = 0u;
                }

        for (int k = 0; k < KITERS; k++) {
            // STS A(k+1) from reg buffer (pre-sync; slot (k+1)&3 drained by sync(k-1))
            sts_a16(aDst + ((k + 1) & 3) * STAGE_B, pa0, pa1);

            asm volatile("cp.async.wait_group 2;" ::: "memory");
            __syncthreads();

            // LDG next A stage (cursor aK of tile tA) into reg buffer
            if (aV) {
                const float* ap = aL + aK * BK;
                pa0 = *reinterpret_cast<const float4*>(ap);
                pa1 = *reinterpret_cast<const float4*>(ap + 4);
            }
            if (++aK == KITERS) {
                aK = 0;
                tA += GRID;
                aV = (tA < NTILES);
                if (aV) aL = X + (size_t)((tA / 9) * BM + arow) * KDIM + ac * 8;
            }

            // cp.async next B stage (cursor bK of tile tB), slot continues mod 4
            if (bV) {
                uint32_t so = (bK & 3) * STAGE_B;
                cp_async16(bDst0 + so, bL + bK * BK);
                cp_async16(bDst1 + so, bL + (size_t)128 * KDIM + bK * BK);
            }
            CP_COMMIT();
            if (++bK == KITERS) {
                bK = 0;
                tB += GRID;
                bV = (tB < NTILES);
                if (bV) bL = W + (size_t)((tB % 9) * BN + arow) * KDIM + ac * 8;
            }

            // ---- compute stage k ----
            uint32_t so = (k & 3) * STAGE_B;
            uint32_t aB = aLds + so;
            uint32_t bB = bLds + so;
            uint32_t (*acc)[8][2] = (k < KITERS / 2) ? acch[0] : acch[1];
#pragma unroll
            for (int ks = 0; ks < 2; ks++) {
                uint32_t a[2][4];
                LDSM_X4(a[0][0], a[0][1], a[0][2], a[0][3], aB + ks * 32);
                LDSM_X4(a[1][0], a[1][1], a[1][2], a[1][3], aB + 16 * AROW_B + ks * 32);
                uint32_t b[8][2];
#pragma unroll
                for (int p = 0; p < 4; p++) {
                    LDSM_X4(b[2 * p][0], b[2 * p][1], b[2 * p + 1][0], b[2 * p + 1][1],
                            bB + p * (16 * AROW_B) + ks * 32);
                }
#pragma unroll
                for (int mi = 0; mi < 2; mi++)
#pragma unroll
                    for (int nj = 0; nj < 8; nj++)
                        MMA16816_F16(acc[mi][nj], a[mi][0], a[mi][1], a[mi][2], a[mi][3],
                                     b[nj][0], b[nj][1]);
            }
        }

        // ---- epilogue (overlaps next tile's in-flight loads) ----
#pragma unroll
        for (int nj = 0; nj < 8; nj++) {
            int c = n0 + warp_n * 64 + nj * 8 + 2 * (lane & 3);
            float2 bb = *reinterpret_cast<const float2*>(bias + c);
#pragma unroll
            for (int mi = 0; mi < 2; mi++) {
                int r = m0 + warp_m * 32 + mi * 16 + (lane >> 2);
                float2 c00 = __half22float2(*reinterpret_cast<__half2*>(&acch[0][mi][nj][0]));
                float2 c01 = __half22float2(*reinterpret_cast<__half2*>(&acch[0][mi][nj][1]));
                float2 c10 = __half22float2(*reinterpret_cast<__half2*>(&acch[1][mi][nj][0]));
                float2 c11 = __half22float2(*reinterpret_cast<__half2*>(&acch[1][mi][nj][1]));
                float2 v0, v1;
                v0.x = c00.x + c10.x + bb.x;
                v0.y = c00.y + c10.y + bb.y;
                v1.x = c01.x + c11.x + bb.x;
                v1.y = c01.y + c11.y + bb.y;
                *reinterpret_cast<float2*>(out + (size_t)r * NDIM + c) = v0;
                *reinterpret_cast<float2*>(out + (size_t)(r + 8) * NDIM + c) = v1;
            }
        }
    }
}

// ---------------- launch ----------------
extern "C" void kernel_launch(void* const* d_in, const int* in_sizes, int n_in,
                              void* d_out, int out_size) {
    (void)in_sizes; (void)n_in; (void)out_size;
    const float* x   = (const float*)d_in[0];
    const float* Wq  = (const float*)d_in[1];
    const float* b   = (const float*)d_in[2];
    const float* Aq  = (const float*)d_in[3];
    const float* Bq  = (const float*)d_in[4];
    const float* Av  = (const float*)d_in[5];
    const float* Bv  = (const float*)d_in[6];
    const float* s0  = (const float*)d_in[7];
    float* out = (float*)d_out;

    __half* wh;
    cudaGetSymbolAddress((void**)&wh, g_Wh);

    prep_w_kernel<<<(NDIM * KDIM) / 256, 256>>>(Wq, Aq, Bq, Av, Bv, s0);

    cudaFuncSetAttribute(gemm_persist,
                         cudaFuncAttributeMaxDynamicSharedMemorySize, SMEM_TOTAL);
    gemm_persist<<<GRID, 512, SMEM_TOTAL>>>(x, wh, b, out);
}

// round 13
// speedup vs baseline: 1.4809x; 1.4809x over previous
#include <cuda_runtime.h>
#include <cuda_fp16.h>
#include <cstdint>

// ---------------- problem constants ----------------
#define MDIM 65536      // B*S
#define KDIM 768        // D
#define NDIM 2304       // 3*D
#define RNK  4

#define BM 128
#define BN 256
#define BK 32           // halves per K-step
#define KITERS (KDIM / BK)   // 24
#define STAGES 4

// smem stage layout: A 128 rows x 80B (32 halves + 16B pad), B 256 rows x 80B
#define AROW_B   80
#define A_BYTES  (128 * AROW_B)      // 10240
#define B_BYTES  (256 * AROW_B)      // 20480
#define STAGE_B  (A_BYTES + B_BYTES) // 30720
#define SMEM_TOTAL (STAGES * STAGE_B) // 122880

// ---------------- device scratch (no allocations allowed) ----------------
__device__ __half g_Wh[(size_t)NDIM * KDIM];   // folded fp16 W_eff (3.4 MB)

// ---------------- helpers ----------------
__device__ __forceinline__ uint32_t smem_u32(const void* p) {
    return (uint32_t)__cvta_generic_to_shared(p);
}

__device__ __forceinline__ void cp_async16(uint32_t s, const void* g) {
    asm volatile("cp.async.cg.shared.global [%0], [%1], 16;" :: "r"(s), "l"(g));
}
#define CP_COMMIT() asm volatile("cp.async.commit_group;" ::: "memory")

#define LDSM_X4(r0, r1, r2, r3, addr) \
    asm volatile("ldmatrix.sync.aligned.m8n8.x4.shared.b16 {%0,%1,%2,%3}, [%4];" \
        : "=r"(r0), "=r"(r1), "=r"(r2), "=r"(r3) : "r"(addr))

// fp16-accumulate MMA (same rate as f32-acc on this chip; halves acc regs)
#define MMA16816_F16(d, a0, a1, a2, a3, b0, b1) \
    asm volatile("mma.sync.aligned.m16n8k16.row.col.f16.f16.f16.f16 " \
        "{%0,%1}, {%2,%3,%4,%5}, {%6,%7}, {%0,%1};" \
        : "+r"((d)[0]), "+r"((d)[1]) \
        : "r"(a0), "r"(a1), "r"(a2), "r"(a3), "r"(b0), "r"(b1))

// convert 8 fp32 -> 8 fp16, store 16B to smem
__device__ __forceinline__ void sts_a16(uint32_t dst, float4 p0, float4 p1) {
    __half2 h0 = __floats2half2_rn(p0.x, p0.y);
    __half2 h1 = __floats2half2_rn(p0.z, p0.w);
    __half2 h2 = __floats2half2_rn(p1.x, p1.y);
    __half2 h3 = __floats2half2_rn(p1.z, p1.w);
    asm volatile("st.shared.v4.b32 [%0], {%1,%2,%3,%4};" :: "r"(dst),
        "r"(*reinterpret_cast<uint32_t*>(&h0)), "r"(*reinterpret_cast<uint32_t*>(&h1)),
        "r"(*reinterpret_cast<uint32_t*>(&h2)), "r"(*reinterpret_cast<uint32_t*>(&h3))
        : "memory");
}

// ---------------- prep kernel (fold LoRA into W, fp16) ----------------
__global__ void prep_w_kernel(const float* __restrict__ W,
                              const float* __restrict__ Aq, const float* __restrict__ Bq,
                              const float* __restrict__ Av, const float* __restrict__ Bv,
                              const float* __restrict__ s0) {
    int idx = blockIdx.x * 256 + threadIdx.x;   // exact: NDIM*KDIM
    int e = idx / KDIM;
    int d = idx - e * KDIM;
    float w = W[idx];
    float s = s0[0];
    if (e < KDIM) {                              // q slice
        float acc = 0.f;
#pragma unroll
        for (int r = 0; r < RNK; r++) acc += Aq[r * KDIM + d] * Bq[e * RNK + r];
        w = fmaf(s, acc, w);
    } else if (e >= 2 * KDIM) {                  // v slice
        int e2 = e - 2 * KDIM;
        float acc = 0.f;
#pragma unroll
        for (int r = 0; r < RNK; r++) acc += Av[r * KDIM + d] * Bv[e2 * RNK + r];
        w = fmaf(s, acc, w);
    }
    g_Wh[idx] = __float2half_rn(w);
}

// --- GEMM (R8 structure): 512 thr, warp 32x64, fp16 acc 2 chains,
// --- A converted fp32->fp16 in-kernel via 1-iter register pipeline.
__global__ __launch_bounds__(512, 1)
void gemm_f16_kernel(const float* __restrict__ X, const __half* __restrict__ W,
                     const float* __restrict__ bias, float* __restrict__ out) {
    extern __shared__ char smem[];
    uint32_t sb = smem_u32(smem);
    int tid = threadIdx.x;
    int lane = tid & 31;
    int wid = tid >> 5;
    int warp_m = wid & 3;     // 4 m-warps
    int warp_n = wid >> 2;    // 4 n-warps

    int n0 = blockIdx.x * BN;   // 9 n-tiles fast-varying (X L2 reuse)
    int m0 = blockIdx.y * BM;

    // ---- per-thread load geometry ----
    int arow = tid >> 2, ac = tid & 3;
    // A: fp32 source, 8 floats (32B) per thread per stage
    const float* aSrc = X + (size_t)(m0 + arow) * KDIM + ac * 8;
    uint32_t aDst = sb + arow * AROW_B + ac * 16;

    // B: fp16 source via cp.async, 2 chunks per thread
    int brow0 = tid >> 2;
    const __half* bSrc0 = W + (size_t)(n0 + brow0) * KDIM + ac * 8;
    const __half* bSrc1 = bSrc0 + (size_t)128 * KDIM;
    uint32_t bDst0 = sb + A_BYTES + brow0 * AROW_B + ac * 16;
    uint32_t bDst1 = bDst0 + 128 * AROW_B;

    // ---- ldmatrix lane addresses (identical to R8) ----
    uint32_t aLds = sb + (warp_m * 32 + (lane & 15)) * AROW_B + ((lane >> 4) * 16);
    int t_ = lane >> 3;
    uint32_t bLds = sb + A_BYTES + (warp_n * 64 + (lane & 7) + (t_ >> 1) * 8) * AROW_B
                    + (t_ & 1) * 16;

    // fp16 accumulators: 2 independent K-chains (accuracy)
    uint32_t acch[2][2][8][2];
#pragma unroll
    for (int c = 0; c < 2; c++)
#pragma unroll
        for (int mi = 0; mi < 2; mi++)
#pragma unroll
            for (int nj = 0; nj < 8; nj++) {
                acch[c][mi][nj][0] = 0u;
                acch[c][mi][nj][1] = 0u;
            }

    // ---- prologue ----
    // B stages 0..2 via cp.async (3 commit groups, matching R8 wait logic)
#pragma unroll
    for (int s = 0; s < STAGES - 1; s++) {
        uint32_t so = s * STAGE_B;
        cp_async16(bDst0 + so, bSrc0 + s * BK);
        cp_async16(bDst1 + so, bSrc1 + s * BK);
        CP_COMMIT();
    }
    // A stage 0: LDG fp32 -> cvt -> STS; then preload stage 1 into regs
    float4 pa0 = *reinterpret_cast<const float4*>(aSrc);
    float4 pa1 = *reinterpret_cast<const float4*>(aSrc + 4);
    sts_a16(aDst, pa0, pa1);
    pa0 = *reinterpret_cast<const float4*>(aSrc + BK);
    pa1 = *reinterpret_cast<const float4*>(aSrc + BK + 4);

    for (int k = 0; k < KITERS; k++) {
        // STS A(k+1) from reg buffer (pre-sync; slot (k+1)&3 drained since k-3)
        sts_a16(aDst + ((k + 1) & 3) * STAGE_B, pa0, pa1);

        asm volatile("cp.async.wait_group 2;" ::: "memory");
        __syncthreads();

        // LDG A stage k+2 (clamped; last iters re-read stage 23 harmlessly)
        {
            int ak = (k + 2 < KITERS) ? (k + 2) : (KITERS - 1);
            const float* ap = aSrc + ak * BK;
            pa0 = *reinterpret_cast<const float4*>(ap);
            pa1 = *reinterpret_cast<const float4*>(ap + 4);
        }

        // cp.async B stage k+3 (slot of stage k-1, drained by sync above)
        int kn = k + STAGES - 1;
        if (kn < KITERS) {
            uint32_t so = (kn & (STAGES - 1)) * STAGE_B;
            cp_async16(bDst0 + so, bSrc0 + kn * BK);
            cp_async16(bDst1 + so, bSrc1 + kn * BK);
        }
        CP_COMMIT();

        // ---- compute stage k ----
        uint32_t so = (k & (STAGES - 1)) * STAGE_B;
        uint32_t aB = aLds + so;
        uint32_t bB = bLds + so;
        uint32_t (*acc)[8][2] = (k < KITERS / 2) ? acch[0] : acch[1];
#pragma unroll
        for (int ks = 0; ks < 2; ks++) {
            uint32_t a[2][4];
            LDSM_X4(a[0][0], a[0][1], a[0][2], a[0][3], aB + ks * 32);
            LDSM_X4(a[1][0], a[1][1], a[1][2], a[1][3], aB + 16 * AROW_B + ks * 32);
            uint32_t b[8][2];
#pragma unroll
            for (int p = 0; p < 4; p++) {
                LDSM_X4(b[2 * p][0], b[2 * p][1], b[2 * p + 1][0], b[2 * p + 1][1],
                        bB + p * (16 * AROW_B) + ks * 32);
            }
#pragma unroll
            for (int mi = 0; mi < 2; mi++)
#pragma unroll
                for (int nj = 0; nj < 8; nj++)
                    MMA16816_F16(acc[mi][nj], a[mi][0], a[mi][1], a[mi][2], a[mi][3],
                                 b[nj][0], b[nj][1]);
        }
    }

    // ---- epilogue: combine chains in fp32, add bias, store ----
#pragma unroll
    for (int nj = 0; nj < 8; nj++) {
        int c = n0 + warp_n * 64 + nj * 8 + 2 * (lane & 3);
        float2 bb = *reinterpret_cast<const float2*>(bias + c);
#pragma unroll
        for (int mi = 0; mi < 2; mi++) {
            int r = m0 + warp_m * 32 + mi * 16 + (lane >> 2);
            float2 c00 = __half22float2(*reinterpret_cast<__half2*>(&acch[0][mi][nj][0]));
            float2 c01 = __half22float2(*reinterpret_cast<__half2*>(&acch[0][mi][nj][1]));
            float2 c10 = __half22float2(*reinterpret_cast<__half2*>(&acch[1][mi][nj][0]));
            float2 c11 = __half22float2(*reinterpret_cast<__half2*>(&acch[1][mi][nj][1]));
            float2 v0, v1;
            v0.x = c00.x + c10.x + bb.x;
            v0.y = c00.y + c10.y + bb.y;
            v1.x = c01.x + c11.x + bb.x;
            v1.y = c01.y + c11.y + bb.y;
            *reinterpret_cast<float2*>(out + (size_t)r * NDIM + c) = v0;
            *reinterpret_cast<float2*>(out + (size_t)(r + 8) * NDIM + c) = v1;
        }
    }
}

// ---------------- launch ----------------
extern "C" void kernel_launch(void* const* d_in, const int* in_sizes, int n_in,
                              void* d_out, int out_size) {
    (void)in_sizes; (void)n_in; (void)out_size;
    const float* x   = (const float*)d_in[0];
    const float* Wq  = (const float*)d_in[1];
    const float* b   = (const float*)d_in[2];
    const float* Aq  = (const float*)d_in[3];
    const float* Bq  = (const float*)d_in[4];
    const float* Av  = (const float*)d_in[5];
    const float* Bv  = (const float*)d_in[6];
    const float* s0  = (const float*)d_in[7];
    float* out = (float*)d_out;

    __half* wh;
    cudaGetSymbolAddress((void**)&wh, g_Wh);

    prep_w_kernel<<<(NDIM * KDIM) / 256, 256>>>(Wq, Aq, Bq, Av, Bv, s0);

    cudaFuncSetAttribute(gemm_f16_kernel,
                         cudaFuncAttributeMaxDynamicSharedMemorySize, SMEM_TOTAL);
    gemm_f16_kernel<<<dim3(NDIM / BN, MDIM / BM, 1), 512, SMEM_TOTAL>>>(
        x, wh, b, out);
}

// round 15
// speedup vs baseline: 1.5123x; 1.0213x over previous
#include <cuda_runtime.h>
#include <cuda_fp16.h>
#include <cstdint>

// ---------------- problem constants ----------------
#define MDIM 65536      // B*S
#define KDIM 768        // D
#define NDIM 2304       // 3*D
#define RNK  4

#define BM 128
#define BN 256
#define BK 32           // halves per K-step
#define KITERS (KDIM / BK)   // 24
#define STAGES 4

// smem stage layout: A 128 rows x 80B (32 halves + 16B pad), B 256 rows x 80B
#define AROW_B   80
#define A_BYTES  (128 * AROW_B)      // 10240
#define B_BYTES  (256 * AROW_B)      // 20480
#define STAGE_B  (A_BYTES + B_BYTES) // 30720
#define SMEM_TOTAL (STAGES * STAGE_B) // 122880

// ---------------- device scratch (no allocations allowed) ----------------
__device__ __half g_Wh[(size_t)NDIM * KDIM];   // folded fp16 W_eff (3.4 MB)

// ---------------- helpers ----------------
__device__ __forceinline__ uint32_t smem_u32(const void* p) {
    return (uint32_t)__cvta_generic_to_shared(p);
}

__device__ __forceinline__ void cp_async16(uint32_t s, const void* g) {
    asm volatile("cp.async.cg.shared.global [%0], [%1], 16;" :: "r"(s), "l"(g));
}
#define CP_COMMIT() asm volatile("cp.async.commit_group;" ::: "memory")

#define LDSM_X4(r0, r1, r2, r3, addr) \
    asm volatile("ldmatrix.sync.aligned.m8n8.x4.shared.b16 {%0,%1,%2,%3}, [%4];" \
        : "=r"(r0), "=r"(r1), "=r"(r2), "=r"(r3) : "r"(addr))

// fp16-accumulate MMA (double-rate HMMA, rt~8/SMSP on sm_103a)
#define MMA16816_F16(d, a0, a1, a2, a3, b0, b1) \
    asm volatile("mma.sync.aligned.m16n8k16.row.col.f16.f16.f16.f16 " \
        "{%0,%1}, {%2,%3,%4,%5}, {%6,%7}, {%0,%1};" \
        : "+r"((d)[0]), "+r"((d)[1]) \
        : "r"(a0), "r"(a1), "r"(a2), "r"(a3), "r"(b0), "r"(b1))

// convert 8 fp32 -> 8 fp16, store 16B to smem
__device__ __forceinline__ void sts_a16(uint32_t dst, float4 p0, float4 p1) {
    __half2 h0 = __floats2half2_rn(p0.x, p0.y);
    __half2 h1 = __floats2half2_rn(p0.z, p0.w);
    __half2 h2 = __floats2half2_rn(p1.x, p1.y);
    __half2 h3 = __floats2half2_rn(p1.z, p1.w);
    asm volatile("st.shared.v4.b32 [%0], {%1,%2,%3,%4};" :: "r"(dst),
        "r"(*reinterpret_cast<uint32_t*>(&h0)), "r"(*reinterpret_cast<uint32_t*>(&h1)),
        "r"(*reinterpret_cast<uint32_t*>(&h2)), "r"(*reinterpret_cast<uint32_t*>(&h3))
        : "memory");
}

// ---------------- prep kernel (fold LoRA into W, fp16) ----------------
__global__ void prep_w_kernel(const float* __restrict__ W,
                              const float* __restrict__ Aq, const float* __restrict__ Bq,
                              const float* __restrict__ Av, const float* __restrict__ Bv,
                              const float* __restrict__ s0) {
    int idx = blockIdx.x * 256 + threadIdx.x;   // exact: NDIM*KDIM
    int e = idx / KDIM;
    int d = idx - e * KDIM;
    float w = W[idx];
    float s = s0[0];
    if (e < KDIM) {                              // q slice
        float acc = 0.f;
#pragma unroll
        for (int r = 0; r < RNK; r++) acc += Aq[r * KDIM + d] * Bq[e * RNK + r];
        w = fmaf(s, acc, w);
    } else if (e >= 2 * KDIM) {                  // v slice
        int e2 = e - 2 * KDIM;
        float acc = 0.f;
#pragma unroll
        for (int r = 0; r < RNK; r++) acc += Av[r * KDIM + d] * Bv[e2 * RNK + r];
        w = fmaf(s, acc, w);
    }
    g_Wh[idx] = __float2half_rn(w);
}

// --- GEMM: 512 thr, warp 32x64, fp16 acc 2 chains, fused fp32->fp16 A path,
// --- B-fragment software pipelining (short ldsm->mma dependency chains).
__global__ __launch_bounds__(512, 1)
void gemm_f16_kernel(const float* __restrict__ X, const __half* __restrict__ W,
                     const float* __restrict__ bias, float* __restrict__ out) {
    extern __shared__ char smem[];
    uint32_t sb = smem_u32(smem);
    int tid = threadIdx.x;
    int lane = tid & 31;
    int wid = tid >> 5;
    int warp_m = wid & 3;     // 4 m-warps
    int warp_n = wid >> 2;    // 4 n-warps

    int n0 = blockIdx.x * BN;   // 9 n-tiles fast-varying (X L2 reuse)
    int m0 = blockIdx.y * BM;

    // ---- per-thread load geometry ----
    int arow = tid >> 2, ac = tid & 3;
    const float* aSrc = X + (size_t)(m0 + arow) * KDIM + ac * 8;
    uint32_t aDst = sb + arow * AROW_B + ac * 16;

    int brow0 = tid >> 2;
    const __half* bSrc0 = W + (size_t)(n0 + brow0) * KDIM + ac * 8;
    const __half* bSrc1 = bSrc0 + (size_t)128 * KDIM;
    uint32_t bDst0 = sb + A_BYTES + brow0 * AROW_B + ac * 16;
    uint32_t bDst1 = bDst0 + 128 * AROW_B;

    // ---- ldmatrix lane addresses ----
    uint32_t aLds = sb + (warp_m * 32 + (lane & 15)) * AROW_B + ((lane >> 4) * 16);
    int t_ = lane >> 3;
    uint32_t bLds = sb + A_BYTES + (warp_n * 64 + (lane & 7) + (t_ >> 1) * 8) * AROW_B
                    + (t_ & 1) * 16;

    // fp16 accumulators: 2 independent K-chains (accuracy)
    uint32_t acch[2][2][8][2];
#pragma unroll
    for (int c = 0; c < 2; c++)
#pragma unroll
        for (int mi = 0; mi < 2; mi++)
#pragma unroll
            for (int nj = 0; nj < 8; nj++) {
                acch[c][mi][nj][0] = 0u;
                acch[c][mi][nj][1] = 0u;
            }

    // ---- prologue ----
#pragma unroll
    for (int s = 0; s < STAGES - 1; s++) {
        uint32_t so = s * STAGE_B;
        cp_async16(bDst0 + so, bSrc0 + s * BK);
        cp_async16(bDst1 + so, bSrc1 + s * BK);
        CP_COMMIT();
    }
    float4 pa0 = *reinterpret_cast<const float4*>(aSrc);
    float4 pa1 = *reinterpret_cast<const float4*>(aSrc + 4);
    sts_a16(aDst, pa0, pa1);
    pa0 = *reinterpret_cast<const float4*>(aSrc + BK);
    pa1 = *reinterpret_cast<const float4*>(aSrc + BK + 4);

    for (int k = 0; k < KITERS; k++) {
        // STS A(k+1) (pre-sync; slot (k+1)&3 drained since k-3)
        sts_a16(aDst + ((k + 1) & 3) * STAGE_B, pa0, pa1);

        asm volatile("cp.async.wait_group 2;" ::: "memory");
        __syncthreads();

        // LDG A stage k+2 (clamped tail re-read is harmless)
        {
            int ak = (k + 2 < KITERS) ? (k + 2) : (KITERS - 1);
            const float* ap = aSrc + ak * BK;
            pa0 = *reinterpret_cast<const float4*>(ap);
            pa1 = *reinterpret_cast<const float4*>(ap + 4);
        }

        // cp.async B stage k+3
        int kn = k + STAGES - 1;
        if (kn < KITERS) {
            uint32_t so = (kn & (STAGES - 1)) * STAGE_B;
            cp_async16(bDst0 + so, bSrc0 + kn * BK);
            cp_async16(bDst1 + so, bSrc1 + kn * BK);
        }
        CP_COMMIT();

        // ---- compute stage k: B-frag pipelined ----
        uint32_t so = (k & (STAGES - 1)) * STAGE_B;
        uint32_t aB = aLds + so;
        uint32_t bB = bLds + so;
        uint32_t (*acc)[8][2] = (k < KITERS / 2) ? acch[0] : acch[1];
#pragma unroll
        for (int ks = 0; ks < 2; ks++) {
            uint32_t a[2][4];
            LDSM_X4(a[0][0], a[0][1], a[0][2], a[0][3], aB + ks * 32);
            LDSM_X4(a[1][0], a[1][1], a[1][2], a[1][3], aB + 16 * AROW_B + ks * 32);
            // double-buffered B frags: one x4 (2 nj frags) in flight
            uint32_t bb[2][4];
            LDSM_X4(bb[0][0], bb[0][1], bb[0][2], bb[0][3], bB + ks * 32);
#pragma unroll
            for (int p = 0; p < 4; p++) {
                if (p < 3)
                    LDSM_X4(bb[(p + 1) & 1][0], bb[(p + 1) & 1][1],
                            bb[(p + 1) & 1][2], bb[(p + 1) & 1][3],
                            bB + (p + 1) * (16 * AROW_B) + ks * 32);
                uint32_t* bc = bb[p & 1];
                MMA16816_F16(acc[0][2 * p],     a[0][0], a[0][1], a[0][2], a[0][3], bc[0], bc[1]);
                MMA16816_F16(acc[0][2 * p + 1], a[0][0], a[0][1], a[0][2], a[0][3], bc[2], bc[3]);
                MMA16816_F16(acc[1][2 * p],     a[1][0], a[1][1], a[1][2], a[1][3], bc[0], bc[1]);
                MMA16816_F16(acc[1][2 * p + 1], a[1][0], a[1][1], a[1][2], a[1][3], bc[2], bc[3]);
            }
        }
    }

    // ---- epilogue: combine chains in fp32, add bias, store ----
#pragma unroll
    for (int nj = 0; nj < 8; nj++) {
        int c = n0 + warp_n * 64 + nj * 8 + 2 * (lane & 3);
        float2 bb = *reinterpret_cast<const float2*>(bias + c);
#pragma unroll
        for (int mi = 0; mi < 2; mi++) {
            int r = m0 + warp_m * 32 + mi * 16 + (lane >> 2);
            float2 c00 = __half22float2(*reinterpret_cast<__half2*>(&acch[0][mi][nj][0]));
            float2 c01 = __half22float2(*reinterpret_cast<__half2*>(&acch[0][mi][nj][1]));
            float2 c10 = __half22float2(*reinterpret_cast<__half2*>(&acch[1][mi][nj][0]));
            float2 c11 = __half22float2(*reinterpret_cast<__half2*>(&acch[1][mi][nj][1]));
            float2 v0, v1;
            v0.x = c00.x + c10.x + bb.x;
            v0.y = c00.y + c10.y + bb.y;
            v1.x = c01.x + c11.x + bb.x;
            v1.y = c01.y + c11.y + bb.y;
            *reinterpret_cast<float2*>(out + (size_t)r * NDIM + c) = v0;
            *reinterpret_cast<float2*>(out + (size_t)(r + 8) * NDIM + c) = v1;
        }
    }
}

// ---------------- launch ----------------
extern "C" void kernel_launch(void* const* d_in, const int* in_sizes, int n_in,
                              void* d_out, int out_size) {
    (void)in_sizes; (void)n_in; (void)out_size;
    const float* x   = (const float*)d_in[0];
    const float* Wq  = (const float*)d_in[1];
    const float* b   = (const float*)d_in[2];
    const float* Aq  = (const float*)d_in[3];
    const float* Bq  = (const float*)d_in[4];
    const float* Av  = (const float*)d_in[5];
    const float* Bv  = (const float*)d_in[6];
    const float* s0  = (const float*)d_in[7];
    float* out = (float*)d_out;

    __half* wh;
    cudaGetSymbolAddress((void**)&wh, g_Wh);

    prep_w_kernel<<<(NDIM * KDIM) / 256, 256>>>(Wq, Aq, Bq, Av, Bv, s0);

    cudaFuncSetAttribute(gemm_f16_kernel,
                         cudaFuncAttributeMaxDynamicSharedMemorySize, SMEM_TOTAL);
    gemm_f16_kernel<<<dim3(NDIM / BN, MDIM / BM, 1), 512, SMEM_TOTAL>>>(
        x, wh, b, out);
}